// round 17
// baseline (speedup 1.0000x reference)
#include <cuda_runtime.h>
#include <math.h>
#include <stdint.h>

// Problem shapes (fixed by the dataset)
#define HW_   (768 * 768)       // pixels
#define NQ_   (HW_ / 4)         // pixel float4 quads
#define S_    8192              // chamfer points per cloud
#define NG_   100000            // gradients / sdf
#define NEQ_  (NG_ / 4)         // eik quads
#define NP_   50000             // consistency points

// Fused-kernel geometry: 2 blocks per SM
#define NTH   256
#define NBLK  296               // 2 blocks x 148 SMs, single wave
#define C_CH  256               // chamfer blocks: 2 dirs x 128 rowblocks(64 rows)
#define NMEM  (NBLK - C_CH)     // 40 streaming blocks
#define RPB   64                // rows per chamfer block
#define CCHUNK 512              // cols staged in smem per chunk
#define NCHUNK (S_ / CCHUNK)    // 16 chunks

// Scratch
__device__ double g_part[NBLK][12];           // per-block term partials
__device__ unsigned long long g_sync[4];      // monotone sync counters (never reset)

// ---------------------------------------------------------------------------
// tf32 helpers
// ---------------------------------------------------------------------------
__device__ __forceinline__ uint32_t tf32_of(float x) {
    uint32_t r;
    asm("cvt.rna.tf32.f32 %0, %1;" : "=r"(r) : "f"(x));
    return r;
}

// ---------------------------------------------------------------------------
// Reductions
// ---------------------------------------------------------------------------
__device__ __forceinline__ float warpSum(float v) {
    #pragma unroll
    for (int o = 16; o > 0; o >>= 1) v += __shfl_down_sync(0xffffffffu, v, o);
    return v;
}
__device__ float blockSum(float v) {
    __shared__ float s[32];
    int lane = threadIdx.x & 31, wid = threadIdx.x >> 5;
    __syncthreads();
    v = warpSum(v);
    if (lane == 0) s[wid] = v;
    __syncthreads();
    v = (threadIdx.x < (NTH / 32)) ? s[threadIdx.x] : 0.0f;
    if (wid == 0) v = warpSum(v);
    return v;
}
__device__ __forceinline__ double dwarpSum(double v) {
    #pragma unroll
    for (int o = 16; o > 0; o >>= 1) v += __shfl_down_sync(0xffffffffu, v, o);
    return v;
}
__device__ double dblockSum(double v) {
    __shared__ double sd[32];
    int lane = threadIdx.x & 31, wid = threadIdx.x >> 5;
    __syncthreads();
    v = dwarpSum(v);
    if (lane == 0) sd[wid] = v;
    __syncthreads();
    v = (threadIdx.x < (NTH / 32)) ? sd[threadIdx.x] : 0.0;
    if (wid == 0) v = dwarpSum(v);
    return v;
}

// ---------------------------------------------------------------------------
// Grid-wide sync (monotone counter, graph-replay safe)
// ---------------------------------------------------------------------------
__device__ __forceinline__ void gridSync(int s) {
    __syncthreads();
    if (threadIdx.x == 0) {
        __threadfence();
        atomicAdd(&g_sync[s], 1ULL);
        while ((*(volatile unsigned long long*)&g_sync[s]) % NBLK != 0ULL)
            __nanosleep(64);
        __threadfence();
    }
    __syncthreads();
}

// ---------------------------------------------------------------------------
// The fused kernel
// ---------------------------------------------------------------------------
__global__ void __launch_bounds__(NTH, 2)
k_fused(const float* __restrict__ npred, const float* __restrict__ ngt,
        const float* __restrict__ dpred, const float* __restrict__ dgt,
        const float* __restrict__ X,     const float* __restrict__ Y,
        const float* __restrict__ mask,  const float* __restrict__ comp,
        const float* __restrict__ grad,  const float* __restrict__ sdf,
        const float* __restrict__ nw,    const float* __restrict__ vis,
        const float* __restrict__ w,     float* __restrict__ out) {
    const int bid  = blockIdx.x;
    const int t    = threadIdx.x;
    const int lane = t & 31;
    const int wid  = t >> 5;

    // ======================= PHASE 1 (role-partitioned, overlapped) ========
    if (bid < C_CH) {
        // ---- chamfer via tf32 mma.sync, split-precision compensated ----
        // Block: 64 src rows x ALL 8192 dest cols. Row mins finalize here.
        __shared__ float bhi[CCHUNK * 4];   // [col][k0..3] = yh'0..2, yyh
        __shared__ float blo[CCHUNK * 8];   // [col][k0..7] = yh'0..2, yl'0..2, yyl, 0
        __shared__ float srm[8][16];        // per-warp row mins

        const int dir    = bid >> 7;           // 0: rows=X, 1: rows=Y
        const int rowblk = bid & 127;
        const float* src = dir ? Y : X;
        const float* dst = dir ? X : Y;

        const int g  = lane >> 2;              // fragment row group 0..7
        const int tk = lane & 3;               // fragment k/col slot 0..3
        const int rg = wid >> 1;               // warp's m16 row group 0..3
        const int ch = (wid & 1) * (CCHUNK / 2); // warp's col half within chunk

        // ---- build A fragments (rows r0 = base+g, r1 = r0+8) ----
        const int rbase = rowblk * RPB + rg * 16;
        uint32_t ahi0, ahi1, alo0, alo1, alo2, alo3;
        {
            const int r0 = rbase + g, r1 = r0 + 8;
            float x0a = __ldg(&src[3 * r0 + 0]), x1a = __ldg(&src[3 * r0 + 1]), x2a = __ldg(&src[3 * r0 + 2]);
            float x0b = __ldg(&src[3 * r1 + 0]), x1b = __ldg(&src[3 * r1 + 1]), x2b = __ldg(&src[3 * r1 + 2]);
            uint32_t h0a = tf32_of(x0a), h1a = tf32_of(x1a), h2a = tf32_of(x2a);
            uint32_t h0b = tf32_of(x0b), h1b = tf32_of(x1b), h2b = tf32_of(x2b);
            uint32_t l0a = tf32_of(x0a - __uint_as_float(h0a));
            uint32_t l1a = tf32_of(x1a - __uint_as_float(h1a));
            uint32_t l2a = tf32_of(x2a - __uint_as_float(h2a));
            uint32_t l0b = tf32_of(x0b - __uint_as_float(h0b));
            uint32_t l1b = tf32_of(x1b - __uint_as_float(h1b));
            uint32_t l2b = tf32_of(x2b - __uint_as_float(h2b));
            const uint32_t ONE = 0x3F800000u, ZERO = 0u;
            // A_hi (k4): slots [xh0, xh1, xh2, 1]
            ahi0 = (tk == 0) ? h0a : (tk == 1) ? h1a : (tk == 2) ? h2a : ONE;
            ahi1 = (tk == 0) ? h0b : (tk == 1) ? h1b : (tk == 2) ? h2b : ONE;
            // A_lo (k8): slots [xl0, xl1, xl2, xh0, xh1, xh2, 1, 0]
            alo0 = (tk == 0) ? l0a : (tk == 1) ? l1a : (tk == 2) ? l2a : h0a; // k = tk
            alo1 = (tk == 0) ? l0b : (tk == 1) ? l1b : (tk == 2) ? l2b : h0b;
            alo2 = (tk == 0) ? h1a : (tk == 1) ? h2a : (tk == 2) ? ONE : ZERO; // k = tk+4
            alo3 = (tk == 0) ? h1b : (tk == 1) ? h2b : (tk == 2) ? ONE : ZERO;
        }

        float rm0 = 3.4e38f, rm1 = 3.4e38f;    // row-min accumulators (p only)

        for (int chunk = 0; chunk < NCHUNK; chunk++) {
            const int c0 = chunk * CCHUNK;
            __syncthreads();                    // prev chunk consumed
            // stage B fragments for CCHUNK cols
            for (int idx = t; idx < CCHUNK; idx += NTH) {
                const int col = c0 + idx;
                float y0 = dst[3 * col + 0];
                float y1 = dst[3 * col + 1];
                float y2 = dst[3 * col + 2];
                float v0 = -2.0f * y0, v1 = -2.0f * y1, v2 = -2.0f * y2;
                float yy = fmaf(y0, y0, fmaf(y1, y1, y2 * y2));
                uint32_t h0 = tf32_of(v0), h1 = tf32_of(v1), h2 = tf32_of(v2);
                uint32_t hy = tf32_of(yy);
                uint32_t p0 = tf32_of(v0 - __uint_as_float(h0));
                uint32_t p1 = tf32_of(v1 - __uint_as_float(h1));
                uint32_t p2 = tf32_of(v2 - __uint_as_float(h2));
                uint32_t py = tf32_of(yy - __uint_as_float(hy));
                bhi[idx * 4 + 0] = __uint_as_float(h0);
                bhi[idx * 4 + 1] = __uint_as_float(h1);
                bhi[idx * 4 + 2] = __uint_as_float(h2);
                bhi[idx * 4 + 3] = __uint_as_float(hy);
                blo[idx * 8 + 0] = __uint_as_float(h0);
                blo[idx * 8 + 1] = __uint_as_float(h1);
                blo[idx * 8 + 2] = __uint_as_float(h2);
                blo[idx * 8 + 3] = __uint_as_float(p0);
                blo[idx * 8 + 4] = __uint_as_float(p1);
                blo[idx * 8 + 5] = __uint_as_float(p2);
                blo[idx * 8 + 6] = __uint_as_float(py);
                blo[idx * 8 + 7] = 0.0f;
            }
            __syncthreads();

            // warp sweeps its 256-col half: 32 n8 tiles
            #pragma unroll 2
            for (int tb = 0; tb < CCHUNK / 2; tb += 8) {
                const int colLocal = ch + tb + g;     // this thread's B col
                uint32_t bh  = __float_as_uint(bhi[colLocal * 4 + tk]);
                uint32_t bl0 = __float_as_uint(blo[colLocal * 8 + tk]);
                uint32_t bl1 = __float_as_uint(blo[colLocal * 8 + tk + 4]);
                float d0, d1, d2, d3;
                asm("mma.sync.aligned.m16n8k4.row.col.f32.tf32.tf32.f32 "
                    "{%0,%1,%2,%3}, {%4,%5}, {%6}, {%7,%8,%9,%10};"
                    : "=f"(d0), "=f"(d1), "=f"(d2), "=f"(d3)
                    : "r"(ahi0), "r"(ahi1), "r"(bh),
                      "f"(0.0f), "f"(0.0f), "f"(0.0f), "f"(0.0f));
                asm("mma.sync.aligned.m16n8k8.row.col.f32.tf32.tf32.f32 "
                    "{%0,%1,%2,%3}, {%4,%5,%6,%7}, {%8,%9}, {%0,%1,%2,%3};"
                    : "+f"(d0), "+f"(d1), "+f"(d2), "+f"(d3)
                    : "r"(alo0), "r"(alo1), "r"(alo2), "r"(alo3),
                      "r"(bl0), "r"(bl1));
                rm0 = fminf(rm0, fminf(d0, d1));
                rm1 = fminf(rm1, fminf(d2, d3));
            }
        }

        // reduce across the 4 tk lanes holding the same rows
        #pragma unroll
        for (int o = 1; o < 4; o <<= 1) {
            rm0 = fminf(rm0, __shfl_xor_sync(0xffffffffu, rm0, o));
            rm1 = fminf(rm1, __shfl_xor_sync(0xffffffffu, rm1, o));
        }
        if (tk == 0) {
            srm[wid][g]     = rm0;
            srm[wid][g + 8] = rm1;
        }
        __syncthreads();

        // combine the two col-half warps per rowgroup, add xx, sqrt, sum
        float ss = 0.f;
        if (t < RPB) {
            const int rgi = t >> 4, inner = t & 15;
            float m = fminf(srm[rgi * 2][inner], srm[rgi * 2 + 1][inner]);
            const int row = rowblk * RPB + rgi * 16 + inner;
            float a = __ldg(&src[3 * row + 0]);
            float b = __ldg(&src[3 * row + 1]);
            float c = __ldg(&src[3 * row + 2]);
            float xx = fmaf(a, a, fmaf(b, b, c * c));
            ss = sqrtf(fmaxf(xx + m, 0.0f));
        }
        float r = blockSum(ss);
        if (t == 0) g_part[bid][10] = (double)r;
    } else {
        // ---------------- streaming role (40 blocks, overlapped) -----------
        const int mb   = bid - C_CH;
        const int gtid = mb * NTH + t;
        const int MT   = NMEM * NTH;

        float cnt = 0.f, nerr = 0.f, den = 0.f, num = 0.f, bce = 0.f;
        const float4* m4p = (const float4*)mask;
        const float4* c4p = (const float4*)comp;
        const float4* g4p = (const float4*)dgt;
        const float4* p4p = (const float4*)dpred;
        const float4* np4 = (const float4*)npred;
        const float4* ng4 = (const float4*)ngt;
        for (int q = gtid; q < NQ_; q += MT) {
            float4 m4 = m4p[q], c4 = c4p[q], g4 = g4p[q], p4 = p4p[q];
            float4 a0 = np4[3 * q + 0], a1 = np4[3 * q + 1], a2 = np4[3 * q + 2];
            float4 b0 = ng4[3 * q + 0], b1 = ng4[3 * q + 1], b2 = ng4[3 * q + 2];
            float m[4] = { m4.x > 0.5f ? 1.f : 0.f, m4.y > 0.5f ? 1.f : 0.f,
                           m4.z > 0.5f ? 1.f : 0.f, m4.w > 0.5f ? 1.f : 0.f };
            float cc[4] = { c4.x, c4.y, c4.z, c4.w };
            float gg[4] = { g4.x, g4.y, g4.z, g4.w };
            float pp[4] = { p4.x, p4.y, p4.z, p4.w };
            float e[4];
            { float d0=a0.x-b0.x, d1=a0.y-b0.y, d2=a0.z-b0.z; e[0]=fmaf(d0,d0,fmaf(d1,d1,d2*d2)); }
            { float d0=a0.w-b0.w, d1=a1.x-b1.x, d2=a1.y-b1.y; e[1]=fmaf(d0,d0,fmaf(d1,d1,d2*d2)); }
            { float d0=a1.z-b1.z, d1=a1.w-b1.w, d2=a2.x-b2.x; e[2]=fmaf(d0,d0,fmaf(d1,d1,d2*d2)); }
            { float d0=a2.y-b2.y, d1=a2.z-b2.z, d2=a2.w-b2.w; e[3]=fmaf(d0,d0,fmaf(d1,d1,d2*d2)); }
            #pragma unroll
            for (int k = 0; k < 4; k++) {
                cnt  += m[k];
                nerr += m[k] * e[k];
                float vg = m[k] * gg[k], vp = m[k] * pp[k];
                den = fmaf(vg, vg, den);
                num = fmaf(vg, vp, num);
                float c = fminf(fmaxf(cc[k], 1e-5f), 1.0f - 1e-5f);
                bce += m[k] * __logf(c) + (1.0f - m[k]) * __logf(1.0f - c);
            }
        }

        float eik = 0.f, sda = 0.f;
        const float4* gr4 = (const float4*)grad;
        const float4* sd4 = (const float4*)sdf;
        for (int q = gtid; q < NEQ_; q += MT) {
            float4 g0 = gr4[3 * q + 0], g1 = gr4[3 * q + 1], g2 = gr4[3 * q + 2];
            float4 s4 = sd4[q];
            float n;
            n = sqrtf(fmaf(g0.x,g0.x,fmaf(g0.y,g0.y,g0.z*g0.z))) - 1.f; eik = fmaf(n,n,eik);
            n = sqrtf(fmaf(g0.w,g0.w,fmaf(g1.x,g1.x,g1.y*g1.y))) - 1.f; eik = fmaf(n,n,eik);
            n = sqrtf(fmaf(g1.z,g1.z,fmaf(g1.w,g1.w,g2.x*g2.x))) - 1.f; eik = fmaf(n,n,eik);
            n = sqrtf(fmaf(g2.y,g2.y,fmaf(g2.z,g2.z,g2.w*g2.w))) - 1.f; eik = fmaf(n,n,eik);
            sda += fabsf(s4.x) + fabsf(s4.y) + fabsf(s4.z) + fabsf(s4.w);
        }

        float con = 0.f, tot = 0.f;
        const float4* nw4  = (const float4*)nw;
        const float4* vs4  = (const float4*)vis;
        for (int p = gtid; p < NP_; p += MT) {
            float wt = w[p];
            float4 v  = vs4[p];
            float4 n0 = nw4[3 * p + 0], n1 = nw4[3 * p + 1], n2 = nw4[3 * p + 2];
            { float vp = v.x*v.y; tot += vp;
              float d0=n0.x-n0.w, d1=n0.y-n1.x, d2=n0.z-n1.y;
              con = fmaf(fmaf(d0,d0,fmaf(d1,d1,d2*d2))*vp, wt, con); }
            { float vp = v.y*v.z; tot += vp;
              float d0=n0.w-n1.z, d1=n1.x-n1.w, d2=n1.y-n2.x;
              con = fmaf(fmaf(d0,d0,fmaf(d1,d1,d2*d2))*vp, wt, con); }
            { float vp = v.z*v.w; tot += vp;
              float d0=n1.z-n2.y, d1=n1.w-n2.z, d2=n2.x-n2.w;
              con = fmaf(fmaf(d0,d0,fmaf(d1,d1,d2*d2))*vp, wt, con); }
        }

        float r;
        r = blockSum(cnt);  if (t == 0) g_part[bid][0] = (double)r;
        r = blockSum(nerr); if (t == 0) g_part[bid][1] = (double)r;
        r = blockSum(den);  if (t == 0) g_part[bid][2] = (double)r;
        r = blockSum(num);  if (t == 0) g_part[bid][3] = (double)r;
        r = blockSum(bce);  if (t == 0) g_part[bid][4] = (double)r;
        r = blockSum(eik);  if (t == 0) g_part[bid][5] = (double)r;
        r = blockSum(sda);  if (t == 0) g_part[bid][6] = (double)r;
        r = blockSum(con);  if (t == 0) g_part[bid][7] = (double)r;
        r = blockSum(tot);  if (t == 0) g_part[bid][8] = (double)r;
    }

    // ======================= SYNC A =======================
    gridSync(0);

    // ======================= PHASE 2 (all blocks): depth second pass =======
    {
        double dden = 0.0, dnum = 0.0;
        #pragma unroll
        for (int i = 0; i < NMEM; i++) {
            dden += g_part[C_CH + i][2];
            dnum += g_part[C_CH + i][3];
        }
        float scale = (float)(dnum / dden);
        if (!isfinite(scale)) scale = 1.0f;

        float ds = 0.f;
        const float4* m4p = (const float4*)mask;
        const float4* g4p = (const float4*)dgt;
        const float4* p4p = (const float4*)dpred;
        for (int q = bid * NTH + t; q < NQ_; q += NBLK * NTH) {
            float4 m4 = m4p[q], g4 = g4p[q], p4 = p4p[q];
            float m;
            m = m4.x > 0.5f ? 1.f : 0.f; ds += fabsf(fmaf(m*g4.x, scale, -(m*p4.x)));
            m = m4.y > 0.5f ? 1.f : 0.f; ds += fabsf(fmaf(m*g4.y, scale, -(m*p4.y)));
            m = m4.z > 0.5f ? 1.f : 0.f; ds += fabsf(fmaf(m*g4.z, scale, -(m*p4.z)));
            m = m4.w > 0.5f ? 1.f : 0.f; ds += fabsf(fmaf(m*g4.w, scale, -(m*p4.w)));
        }
        float r = blockSum(ds);
        if (t == 0) g_part[bid][9] = (double)r;
    }

    // ======================= SYNC B =======================
    gridSync(1);

    // ======================= FINAL (block 0) =======================
    if (bid == 0) {
        double sum[11];
        #pragma unroll
        for (int term = 0; term < 9; term++) {
            double v = (t < NMEM) ? g_part[C_CH + t][term] : 0.0;
            sum[term] = dblockSum(v);
        }
        {   // depth partials span all 296 blocks; fold two per thread
            double v = g_part[t][9];
            if (t + NTH < NBLK) v += g_part[t + NTH][9];
            sum[9] = dblockSum(v);
        }
        {   // chamfer partials: blocks 0..255
            double v = (t < C_CH) ? g_part[t][10] : 0.0;
            sum[10] = dblockSum(v);
        }

        if (t == 0) {
            double mask_sum = sum[0] + 1e-5;
            double normal_loss = sum[1] / mask_sum;

            double den = sum[2];
            double depth_loss = sum[9] / (mask_sum + 1e-8);
            if (den < 1e-10) depth_loss = 0.0;
            if (!isfinite(depth_loss)) depth_loss = 0.0;

            double pc_loss   = sum[10] / (double)S_;
            double mask_loss = -sum[4] / (double)HW_;
            double eik_loss  = sum[5] / (double)NG_;
            double sdf_loss  = sum[6] / (double)NG_;
            double con_loss  = (sum[8] > 0.0) ? (sum[7] / sum[8]) : 0.0;

            out[0] = (float)(normal_loss + depth_loss + pc_loss + mask_loss +
                             eik_loss + sdf_loss + con_loss);
        }
    }
}

// ---------------------------------------------------------------------------
// Launch
// ---------------------------------------------------------------------------
extern "C" void kernel_launch(void* const* d_in, const int* in_sizes, int n_in,
                              void* d_out, int out_size) {
    const float* normal_pred = (const float*)d_in[0];
    const float* normal_gt   = (const float*)d_in[1];
    const float* depth_pred  = (const float*)d_in[2];
    const float* depth_gt    = (const float*)d_in[3];
    const float* X           = (const float*)d_in[4];
    const float* Y           = (const float*)d_in[5];
    const float* mask        = (const float*)d_in[6];
    const float* comp_mask   = (const float*)d_in[7];
    const float* gradients   = (const float*)d_in[8];
    const float* sdf         = (const float*)d_in[9];
    const float* nw_all      = (const float*)d_in[10];
    const float* vis_mask    = (const float*)d_in[11];
    const float* weights     = (const float*)d_in[12];
    float* out = (float*)d_out;

    k_fused<<<NBLK, NTH>>>(normal_pred, normal_gt, depth_pred, depth_gt,
                           X, Y, mask, comp_mask, gradients, sdf,
                           nw_all, vis_mask, weights, out);
}